// round 1
// baseline (speedup 1.0000x reference)
#include <cuda_runtime.h>

#define Bb 128
#define Nn 1024
#define DMdim 64
#define Ssup 2
#define K2 2048   // Ssup * Nn

// Scratch (no allocs allowed): 32 + 64 + 32 = 128 MB static device globals
__device__ float g_xin[Bb * DMdim * Nn];
__device__ float g_y[Bb * DMdim * K2];
__device__ float g_gc[Bb * DMdim * Nn];

// ---------------------------------------------------------------------------
// Kernel 1: x_in[b, o, n] = b_in[o] + W_in[o,:] . concat(x, m, u, h)[b, :, n]
// One thread per (b, n) column.
// ---------------------------------------------------------------------------
__global__ __launch_bounds__(256) void k_in(
    const float* __restrict__ x, const float* __restrict__ m,
    const float* __restrict__ u, const float* __restrict__ h,
    const float* __restrict__ W_in, const float* __restrict__ b_in)
{
    __shared__ float Ws[DMdim * 68];
    __shared__ float bs[DMdim];
    for (int i = threadIdx.x; i < DMdim * 68; i += 256) Ws[i] = W_in[i];
    if (threadIdx.x < DMdim) bs[threadIdx.x] = b_in[threadIdx.x];
    __syncthreads();

    int idx = blockIdx.x * 256 + threadIdx.x;
    int b = idx >> 10;
    int n = idx & 1023;

    float acc[DMdim];
#pragma unroll
    for (int o = 0; o < DMdim; o++) acc[o] = bs[o];

    float v;
    v = x[b * Nn + n];
#pragma unroll
    for (int o = 0; o < DMdim; o++) acc[o] = fmaf(v, Ws[o * 68 + 0], acc[o]);
    v = m[b * Nn + n];
#pragma unroll
    for (int o = 0; o < DMdim; o++) acc[o] = fmaf(v, Ws[o * 68 + 1], acc[o]);
    v = u[(b * 2 + 0) * Nn + n];
#pragma unroll
    for (int o = 0; o < DMdim; o++) acc[o] = fmaf(v, Ws[o * 68 + 2], acc[o]);
    v = u[(b * 2 + 1) * Nn + n];
#pragma unroll
    for (int o = 0; o < DMdim; o++) acc[o] = fmaf(v, Ws[o * 68 + 3], acc[o]);

    for (int c = 0; c < 64; c++) {
        v = h[(b * 64 + c) * Nn + n];
#pragma unroll
        for (int o = 0; o < DMdim; o++) acc[o] = fmaf(v, Ws[o * 68 + 4 + c], acc[o]);
    }

#pragma unroll
    for (int o = 0; o < DMdim; o++) g_xin[(b * 64 + o) * Nn + n] = acc[o];
}

// ---------------------------------------------------------------------------
// Kernel 2: y[b, o, s*Nn + n] = sum_c W_gc[o, s*64+c] * x_in[b, c, n]
// (folds the graph-conv mixing weight into the pre-aggregation space so the
//  per-support aggregation becomes one big GEMM over K = S*Nn)
// ---------------------------------------------------------------------------
__global__ __launch_bounds__(256) void k_y(const float* __restrict__ W_gc)
{
    __shared__ float Wg[DMdim * 128];
    for (int i = threadIdx.x; i < DMdim * 128; i += 256) Wg[i] = W_gc[i];
    __syncthreads();

    int idx = blockIdx.x * 256 + threadIdx.x;
    int b = idx >> 10;
    int n = idx & 1023;

    float xin[64];
#pragma unroll
    for (int c = 0; c < 64; c++) xin[c] = g_xin[(b * 64 + c) * Nn + n];

    for (int s = 0; s < Ssup; s++) {
        for (int o = 0; o < 64; o++) {
            float acc = 0.f;
#pragma unroll
            for (int c = 0; c < 64; c++)
                acc = fmaf(xin[c], Wg[o * 128 + s * 64 + c], acc);
            g_y[(b * 64 + o) * K2 + s * Nn + n] = acc;
        }
    }
}

// ---------------------------------------------------------------------------
// Kernel 3 (dominant): gc[m, w] = b_gc[m%64] + sum_k y[m, k] * adjK(w, k)
//   m = b*64+o  (M = 8192),  w in [0,1024),  k = s*1024+v (K = 2048)
//   adjK(w, k) = adj[s*N*N + w*N + v]
// 128x128x16 tiled fp32 SIMT GEMM, 8x8 per thread, 256 threads.
// ---------------------------------------------------------------------------
#define TBM 128
#define TBN 128
#define TBK 16

__global__ __launch_bounds__(256) void k_gemm(
    const float* __restrict__ adj, const float* __restrict__ b_gc)
{
    __shared__ float As[TBK][TBM + 4];
    __shared__ float Bs[TBK][TBN + 4];

    int tid = threadIdx.x;
    int bm = blockIdx.y * TBM;
    int bn = blockIdx.x * TBN;
    int tx = tid & 15;   // 0..15 -> n
    int ty = tid >> 4;   // 0..15 -> m

    float acc[8][8];
#pragma unroll
    for (int i = 0; i < 8; i++)
#pragma unroll
        for (int j = 0; j < 8; j++) acc[i][j] = 0.f;

    int lr = tid >> 2;        // 0..63 : row within tile (x2 with +64)
    int lc = (tid & 3) * 4;   // 0,4,8,12 : k offset

    for (int k0 = 0; k0 < K2; k0 += TBK) {
        int s = k0 >> 10;
        int v0 = k0 & 1023;

#pragma unroll
        for (int rr = 0; rr < 2; rr++) {
            float4 a4 = *(const float4*)&g_y[(size_t)(bm + lr + rr * 64) * K2 + k0 + lc];
            As[lc + 0][lr + rr * 64] = a4.x;
            As[lc + 1][lr + rr * 64] = a4.y;
            As[lc + 2][lr + rr * 64] = a4.z;
            As[lc + 3][lr + rr * 64] = a4.w;
        }
#pragma unroll
        for (int rr = 0; rr < 2; rr++) {
            float4 b4 = *(const float4*)&adj[(size_t)s * Nn * Nn +
                                             (size_t)(bn + lr + rr * 64) * Nn + v0 + lc];
            Bs[lc + 0][lr + rr * 64] = b4.x;
            Bs[lc + 1][lr + rr * 64] = b4.y;
            Bs[lc + 2][lr + rr * 64] = b4.z;
            Bs[lc + 3][lr + rr * 64] = b4.w;
        }
        __syncthreads();

#pragma unroll
        for (int k = 0; k < TBK; k++) {
            float af[8], bf[8];
#pragma unroll
            for (int i = 0; i < 8; i++) af[i] = As[k][ty * 8 + i];
#pragma unroll
            for (int j = 0; j < 8; j++) bf[j] = Bs[k][tx * 8 + j];
#pragma unroll
            for (int i = 0; i < 8; i++)
#pragma unroll
                for (int j = 0; j < 8; j++)
                    acc[i][j] = fmaf(af[i], bf[j], acc[i][j]);
        }
        __syncthreads();
    }

#pragma unroll
    for (int i = 0; i < 8; i++) {
        int row = ty * 8 + i;                 // 0..127 ; bm % 64 == 0
        float bias = __ldg(&b_gc[row & 63]);
        int mrow = bm + row;
#pragma unroll
        for (int j = 0; j < 8; j++)
            g_gc[(size_t)mrow * Nn + bn + tx * 8 + j] = acc[i][j] + bias;
    }
}

// ---------------------------------------------------------------------------
// Kernel 4: fused W_out conv + PReLU + concat-with-h + readout conv.
// out layout: [read (B*N)] then [out2 (B*128*N)] (tuple order).
// ---------------------------------------------------------------------------
__global__ __launch_bounds__(256) void k_out(
    const float* __restrict__ h, const float* __restrict__ W_out,
    const float* __restrict__ b_out, const float* __restrict__ W_read,
    const float* __restrict__ b_read, const float* __restrict__ prelu_w,
    float* __restrict__ out)
{
    __shared__ float Wo[64 * 128];
    __shared__ float Wr[128];
    __shared__ float bo[64];
    for (int i = threadIdx.x; i < 64 * 128; i += 256) Wo[i] = W_out[i];
    if (threadIdx.x < 128) Wr[threadIdx.x] = W_read[threadIdx.x];
    if (threadIdx.x < 64) bo[threadIdx.x] = b_out[threadIdx.x];
    __syncthreads();

    int idx = blockIdx.x * 256 + threadIdx.x;
    int b = idx >> 10;
    int n = idx & 1023;

    float gcv[64], hv[64];
#pragma unroll
    for (int c = 0; c < 64; c++) gcv[c] = g_gc[(b * 64 + c) * Nn + n];
#pragma unroll
    for (int c = 0; c < 64; c++) hv[c] = h[(b * 64 + c) * Nn + n];

    float pw = __ldg(prelu_w);
    float racc = __ldg(b_read);
    float* out2 = out + (size_t)Bb * Nn;

    for (int o = 0; o < 64; o++) {
        float acc = bo[o];
#pragma unroll
        for (int c = 0; c < 64; c++) acc = fmaf(gcv[c], Wo[o * 128 + c], acc);
#pragma unroll
        for (int c = 0; c < 64; c++) acc = fmaf(hv[c], Wo[o * 128 + 64 + c], acc);
        float p = acc >= 0.f ? acc : pw * acc;
        out2[(size_t)(b * 128 + o) * Nn + n] = p;
        racc = fmaf(Wr[o], p, racc);
    }
#pragma unroll
    for (int c = 0; c < 64; c++) {
        out2[(size_t)(b * 128 + 64 + c) * Nn + n] = hv[c];
        racc = fmaf(Wr[64 + c], hv[c], racc);
    }
    out[b * Nn + n] = racc;
}

// ---------------------------------------------------------------------------
extern "C" void kernel_launch(void* const* d_in, const int* in_sizes, int n_in,
                              void* d_out, int out_size)
{
    const float* x      = (const float*)d_in[0];
    const float* m      = (const float*)d_in[1];
    const float* u      = (const float*)d_in[2];
    const float* h      = (const float*)d_in[3];
    const float* adj    = (const float*)d_in[4];
    const float* W_in   = (const float*)d_in[5];
    const float* b_in   = (const float*)d_in[6];
    const float* W_gc   = (const float*)d_in[7];
    const float* b_gc   = (const float*)d_in[8];
    const float* W_out  = (const float*)d_in[9];
    const float* b_out  = (const float*)d_in[10];
    const float* W_read = (const float*)d_in[11];
    const float* b_read = (const float*)d_in[12];
    const float* prelu  = (const float*)d_in[13];
    float* out = (float*)d_out;

    int cols = Bb * Nn;  // 131072 (b,n) columns

    k_in<<<cols / 256, 256>>>(x, m, u, h, W_in, b_in);
    k_y<<<cols / 256, 256>>>(W_gc);
    dim3 g(Nn / TBN, (Bb * DMdim) / TBM);  // (8, 64)
    k_gemm<<<g, 256>>>(adj, b_gc);
    k_out<<<cols / 256, 256>>>(h, W_out, b_out, W_read, b_read, prelu, out);
}

// round 3
// speedup vs baseline: 1.6042x; 1.6042x over previous
#include <cuda_runtime.h>
#include <cuda_bf16.h>

#define Bb 128
#define Nn 1024
#define DMdim 64
#define Ssup 2
#define K2 2048   // Ssup * Nn

// Scratch (no allocs): static device globals
__device__ float g_gc[Bb * DMdim * Nn];                  // 32 MB
__device__ __nv_bfloat16 g_yhi[(size_t)8192 * 2048];     // 32 MB
__device__ __nv_bfloat16 g_ylo[(size_t)8192 * 2048];     // 32 MB
__device__ __nv_bfloat16 g_ahi[2 * 1024 * 1024];         // 4 MB
__device__ __nv_bfloat16 g_alo[2 * 1024 * 1024];         // 4 MB

// ---------------------------------------------------------------------------
// helpers
// ---------------------------------------------------------------------------
__device__ __forceinline__ unsigned s2u(const void* p) {
    unsigned a;
    asm("{ .reg .u64 t; cvta.to.shared.u64 t, %1; cvt.u32.u64 %0, t; }"
        : "=r"(a) : "l"(p));
    return a;
}

#define CP16(dst, src) \
    asm volatile("cp.async.cg.shared.global [%0], [%1], 16;" :: "r"(dst), "l"(src))
#define CP_COMMIT() asm volatile("cp.async.commit_group;" ::: "memory")

// ---------------------------------------------------------------------------
// Kernel 1: split adj into hi/lo bf16
// ---------------------------------------------------------------------------
__global__ __launch_bounds__(256) void k_adj(const float* __restrict__ adj)
{
    int i = blockIdx.x * 256 + threadIdx.x;   // over 2M/4 = 524288 float4s
    float4 v = ((const float4*)adj)[i];
    __nv_bfloat16 h0 = __float2bfloat16(v.x);
    __nv_bfloat16 h1 = __float2bfloat16(v.y);
    __nv_bfloat16 h2 = __float2bfloat16(v.z);
    __nv_bfloat16 h3 = __float2bfloat16(v.w);
    __nv_bfloat16 l0 = __float2bfloat16(v.x - __bfloat162float(h0));
    __nv_bfloat16 l1 = __float2bfloat16(v.y - __bfloat162float(h1));
    __nv_bfloat16 l2 = __float2bfloat16(v.z - __bfloat162float(h2));
    __nv_bfloat16 l3 = __float2bfloat16(v.w - __bfloat162float(h3));
    ((__nv_bfloat162*)g_ahi)[i * 2 + 0] = __halves2bfloat162(h0, h1);
    ((__nv_bfloat162*)g_ahi)[i * 2 + 1] = __halves2bfloat162(h2, h3);
    ((__nv_bfloat162*)g_alo)[i * 2 + 0] = __halves2bfloat162(l0, l1);
    ((__nv_bfloat162*)g_alo)[i * 2 + 1] = __halves2bfloat162(l2, l3);
}

// ---------------------------------------------------------------------------
// Kernel 2: fused input conv + W_gc fold, split-bf16 output.
// xin[b,:,n] computed in registers, then
// y[(b*64+o), s*1024+n] = sum_c W_gc[o, s*64+c] * xin[c]  as (hi, lo) bf16.
// ---------------------------------------------------------------------------
__global__ __launch_bounds__(256) void k_iny(
    const float* __restrict__ x, const float* __restrict__ m,
    const float* __restrict__ u, const float* __restrict__ h,
    const float* __restrict__ W_in, const float* __restrict__ b_in,
    const float* __restrict__ W_gc)
{
    __shared__ float Ws[DMdim * 68];
    __shared__ float Wg[DMdim * 128];
    __shared__ float bs[DMdim];
    for (int i = threadIdx.x; i < DMdim * 68; i += 256) Ws[i] = W_in[i];
    for (int i = threadIdx.x; i < DMdim * 128; i += 256) Wg[i] = W_gc[i];
    if (threadIdx.x < DMdim) bs[threadIdx.x] = b_in[threadIdx.x];
    __syncthreads();

    int idx = blockIdx.x * 256 + threadIdx.x;
    int b = idx >> 10;
    int n = idx & 1023;

    float xin[DMdim];
#pragma unroll
    for (int o = 0; o < DMdim; o++) xin[o] = bs[o];

    float v;
    v = x[b * Nn + n];
#pragma unroll
    for (int o = 0; o < DMdim; o++) xin[o] = fmaf(v, Ws[o * 68 + 0], xin[o]);
    v = m[b * Nn + n];
#pragma unroll
    for (int o = 0; o < DMdim; o++) xin[o] = fmaf(v, Ws[o * 68 + 1], xin[o]);
    v = u[(b * 2 + 0) * Nn + n];
#pragma unroll
    for (int o = 0; o < DMdim; o++) xin[o] = fmaf(v, Ws[o * 68 + 2], xin[o]);
    v = u[(b * 2 + 1) * Nn + n];
#pragma unroll
    for (int o = 0; o < DMdim; o++) xin[o] = fmaf(v, Ws[o * 68 + 3], xin[o]);

    for (int c = 0; c < 64; c++) {
        v = h[(b * 64 + c) * Nn + n];
#pragma unroll
        for (int o = 0; o < DMdim; o++) xin[o] = fmaf(v, Ws[o * 68 + 4 + c], xin[o]);
    }

    // fold W_gc: 128 outputs (2 supports x 64)
    for (int s = 0; s < Ssup; s++) {
        for (int o = 0; o < 64; o++) {
            float acc = 0.f;
#pragma unroll
            for (int c = 0; c < 64; c++)
                acc = fmaf(xin[c], Wg[o * 128 + s * 64 + c], acc);
            size_t yi = (size_t)(b * 64 + o) * K2 + s * Nn + n;
            __nv_bfloat16 hi = __float2bfloat16(acc);
            g_yhi[yi] = hi;
            g_ylo[yi] = __float2bfloat16(acc - __bfloat162float(hi));
        }
    }
}

// ---------------------------------------------------------------------------
// Kernel 3: mma.sync bf16 GEMM (sm_80-class path; tcgen05 PTX rejected by
// this harness's plain-sm_103 ptxas target).
//   gc[m, w] = b_gc[m&63] + sum over 3 passes of Apass[m,k] * Bpass[w,k]
//   pass 0: (yhi, ahi)   pass 1: (ylo, ahi)   pass 2: (yhi, alo)
// BM=128 BN=128 BK=32, 8 warps (4x2), warp tile 32x64, double-buffered
// cp.async, padded smem rows (40 bf16) for conflict-free ldmatrix.
// ---------------------------------------------------------------------------
#define BM 128
#define BN 128
#define BK 32
#define RS 40            // smem row stride in bf16 (80 bytes, 16B-aligned)
#define STG (128 * RS)   // elems per stage buffer

__device__ __forceinline__ void ldsm4(unsigned* r, unsigned addr) {
    asm volatile("ldmatrix.sync.aligned.m8n8.x4.shared.b16 {%0,%1,%2,%3}, [%4];"
                 : "=r"(r[0]), "=r"(r[1]), "=r"(r[2]), "=r"(r[3]) : "r"(addr));
}
__device__ __forceinline__ void mma16816(float* c, const unsigned* a,
                                         unsigned b0, unsigned b1) {
    asm volatile(
        "mma.sync.aligned.m16n8k16.row.col.f32.bf16.bf16.f32 "
        "{%0,%1,%2,%3}, {%4,%5,%6,%7}, {%8,%9}, {%0,%1,%2,%3};"
        : "+f"(c[0]), "+f"(c[1]), "+f"(c[2]), "+f"(c[3])
        : "r"(a[0]), "r"(a[1]), "r"(a[2]), "r"(a[3]), "r"(b0), "r"(b1));
}

__global__ __launch_bounds__(256) void k_gemm_mma(const float* __restrict__ b_gc)
{
    __shared__ __nv_bfloat16 As[2 * STG];
    __shared__ __nv_bfloat16 Bs[2 * STG];

    int tid = threadIdx.x;
    int lane = tid & 31;
    int wid = tid >> 5;
    int wm = wid >> 1;        // 0..3
    int wn = wid & 1;         // 0..1
    int bm = blockIdx.y * BM;
    int bn = blockIdx.x * BN;

    unsigned aBase = s2u(As);
    unsigned bBase = s2u(Bs);

    float acc[2][8][4];
#pragma unroll
    for (int i = 0; i < 2; i++)
#pragma unroll
        for (int j = 0; j < 8; j++)
#pragma unroll
            for (int q = 0; q < 4; q++) acc[i][j][q] = 0.f;

    // chunk t in [0, 192): pass p = t/64, k-chunk kc = t%64, k0 = kc*32
#define LOAD_CHUNK(t, buf) do {                                                \
    int _p = (t) >> 6;                                                         \
    int _k0 = ((t) & 63) * BK;                                                 \
    int _s = _k0 >> 10;                                                        \
    int _v0 = _k0 & 1023;                                                      \
    const __nv_bfloat16* _Ap = (_p == 1) ? g_ylo : g_yhi;                      \
    const __nv_bfloat16* _Bp = (_p == 2) ? g_alo : g_ahi;                      \
    _Pragma("unroll")                                                          \
    for (int _i = 0; _i < 2; _i++) {                                           \
        int _u = tid + _i * 256;                                               \
        int _row = _u >> 2, _j = _u & 3;                                       \
        unsigned _da = aBase + ((buf) * STG + _row * RS + _j * 8) * 2;         \
        CP16(_da, (const char*)(_Ap + (size_t)(bm + _row) * K2 + _k0 + _j * 8));\
        unsigned _db = bBase + ((buf) * STG + _row * RS + _j * 8) * 2;         \
        CP16(_db, (const char*)(_Bp + (size_t)_s * 1048576 +                   \
                                (size_t)(bn + _row) * 1024 + _v0 + _j * 8));   \
    }                                                                          \
    CP_COMMIT();                                                               \
} while (0)

    LOAD_CHUNK(0, 0);
    LOAD_CHUNK(1, 1);

    for (int t = 0; t < 192; t++) {
        int buf = t & 1;
        if (t == 191) asm volatile("cp.async.wait_group 0;" ::: "memory");
        else          asm volatile("cp.async.wait_group 1;" ::: "memory");
        __syncthreads();

        unsigned abuf = aBase + buf * STG * 2;
        unsigned bbuf = bBase + buf * STG * 2;

#pragma unroll
        for (int kk = 0; kk < 2; kk++) {
            int kb = kk * 16;
            unsigned ar[2][4];
#pragma unroll
            for (int mf = 0; mf < 2; mf++) {
                int mrow = wm * 32 + mf * 16 + (lane & 7) + ((lane >> 3) & 1) * 8;
                int kcol = kb + (lane >> 4) * 8;
                ldsm4(ar[mf], abuf + (mrow * RS + kcol) * 2);
            }
            unsigned br[4][4];
#pragma unroll
            for (int nt = 0; nt < 4; nt++) {
                int nrow = wn * 64 + nt * 16 + (lane & 7) + (lane >> 4) * 8;
                int kcol = kb + ((lane >> 3) & 1) * 8;
                ldsm4(br[nt], bbuf + (nrow * RS + kcol) * 2);
            }
#pragma unroll
            for (int mf = 0; mf < 2; mf++)
#pragma unroll
                for (int nt = 0; nt < 4; nt++) {
                    mma16816(acc[mf][nt * 2 + 0], ar[mf], br[nt][0], br[nt][1]);
                    mma16816(acc[mf][nt * 2 + 1], ar[mf], br[nt][2], br[nt][3]);
                }
        }
        __syncthreads();
        if (t + 2 < 192) LOAD_CHUNK(t + 2, buf);
    }

    // epilogue: add bias, store fp32 to g_gc
#pragma unroll
    for (int mf = 0; mf < 2; mf++) {
        int r0 = bm + wm * 32 + mf * 16 + (lane >> 2);
        float bv0 = __ldg(&b_gc[r0 & 63]);
        float bv1 = __ldg(&b_gc[(r0 + 8) & 63]);
#pragma unroll
        for (int nf = 0; nf < 8; nf++) {
            int col = bn + wn * 64 + nf * 8 + (lane & 3) * 2;
            float2 v0 = make_float2(acc[mf][nf][0] + bv0, acc[mf][nf][1] + bv0);
            float2 v1 = make_float2(acc[mf][nf][2] + bv1, acc[mf][nf][3] + bv1);
            *(float2*)&g_gc[(size_t)r0 * 1024 + col] = v0;
            *(float2*)&g_gc[(size_t)(r0 + 8) * 1024 + col] = v1;
        }
    }
}

// ---------------------------------------------------------------------------
// Kernel 4: fused W_out conv + PReLU + concat + readout (known-good)
// ---------------------------------------------------------------------------
__global__ __launch_bounds__(256) void k_out(
    const float* __restrict__ h, const float* __restrict__ W_out,
    const float* __restrict__ b_out, const float* __restrict__ W_read,
    const float* __restrict__ b_read, const float* __restrict__ prelu_w,
    float* __restrict__ out)
{
    __shared__ float Wo[64 * 128];
    __shared__ float Wr[128];
    __shared__ float bo[64];
    for (int i = threadIdx.x; i < 64 * 128; i += 256) Wo[i] = W_out[i];
    if (threadIdx.x < 128) Wr[threadIdx.x] = W_read[threadIdx.x];
    if (threadIdx.x < 64) bo[threadIdx.x] = b_out[threadIdx.x];
    __syncthreads();

    int idx = blockIdx.x * 256 + threadIdx.x;
    int b = idx >> 10;
    int n = idx & 1023;

    float gcv[64], hv[64];
#pragma unroll
    for (int c = 0; c < 64; c++) gcv[c] = g_gc[(b * 64 + c) * Nn + n];
#pragma unroll
    for (int c = 0; c < 64; c++) hv[c] = h[(b * 64 + c) * Nn + n];

    float pw = __ldg(prelu_w);
    float racc = __ldg(b_read);
    float* out2 = out + (size_t)Bb * Nn;

    for (int o = 0; o < 64; o++) {
        float acc = bo[o];
#pragma unroll
        for (int c = 0; c < 64; c++) acc = fmaf(gcv[c], Wo[o * 128 + c], acc);
#pragma unroll
        for (int c = 0; c < 64; c++) acc = fmaf(hv[c], Wo[o * 128 + 64 + c], acc);
        float p = acc >= 0.f ? acc : pw * acc;
        out2[(size_t)(b * 128 + o) * Nn + n] = p;
        racc = fmaf(Wr[o], p, racc);
    }
#pragma unroll
    for (int c = 0; c < 64; c++) {
        out2[(size_t)(b * 128 + 64 + c) * Nn + n] = hv[c];
        racc = fmaf(Wr[64 + c], hv[c], racc);
    }
    out[b * Nn + n] = racc;
}

// ---------------------------------------------------------------------------
extern "C" void kernel_launch(void* const* d_in, const int* in_sizes, int n_in,
                              void* d_out, int out_size)
{
    const float* x      = (const float*)d_in[0];
    const float* m      = (const float*)d_in[1];
    const float* u      = (const float*)d_in[2];
    const float* h      = (const float*)d_in[3];
    const float* adj    = (const float*)d_in[4];
    const float* W_in   = (const float*)d_in[5];
    const float* b_in   = (const float*)d_in[6];
    const float* W_gc   = (const float*)d_in[7];
    const float* b_gc   = (const float*)d_in[8];
    const float* W_out  = (const float*)d_in[9];
    const float* b_out  = (const float*)d_in[10];
    const float* W_read = (const float*)d_in[11];
    const float* b_read = (const float*)d_in[12];
    const float* prelu  = (const float*)d_in[13];
    float* out = (float*)d_out;

    int cols = Bb * Nn;  // 131072 columns

    k_adj<<<2048, 256>>>(adj);
    k_iny<<<cols / 256, 256>>>(x, m, u, h, W_in, b_in, W_gc);
    dim3 g(Nn / BN, (Bb * DMdim) / BM);   // (8, 64) = 512 CTAs
    k_gemm_mma<<<g, 256>>>(b_gc);
    k_out<<<cols / 256, 256>>>(h, W_out, b_out, W_read, b_read, prelu, out);
}